// round 1
// baseline (speedup 1.0000x reference)
#include <cuda_runtime.h>
#include <math.h>

#define BDIM 8
#define LDIM 1024
#define DDIM 512
#define NST  16
#define NMEL 40
#define NCH  16
#define TCH  (LDIM/NCH)   // 64
#define ROWW 40           // padded row width: [0]=dtsum, [4..19]=B_eff, [20..35]=C

// Scratch (device globals; no allocations allowed)
__device__ float g_row [BDIM*LDIM*ROWW];        // 1.25 MB
__device__ float g_cum [BDIM*LDIM*DDIM];        // 16 MB  (chunk-local cumulative delta)
__device__ float g_hend[BDIM*NCH*NST*DDIM];     // 4 MB   (chunk-local final states)
__device__ float g_hin [BDIM*NCH*NST*DDIM];     // 4 MB   (true incoming states per chunk)

__device__ __forceinline__ float fex2(float x){
    float r; asm("ex2.approx.f32 %0,%1;" : "=f"(r) : "f"(x)); return r;
}
__device__ __forceinline__ float softplusf(float z){
    return (z > 15.f) ? z : __logf(1.f + __expf(z));
}

// Load A2[n] = log2(e) * A[d,n] = -exp(A_log[d,n])*log2e, and detect the
// "integer ratio" structure A2[n] == (n+1)*A2[0] (true for this dataset:
// A_log = log(1..16)), which lets dA_n = p^(n+1) with a single ex2.
__device__ __forceinline__ bool load_A2(const float* __restrict__ Alog, int d,
                                        float (&A2)[NST], float &a1)
{
    const float LOG2E = 1.4426950408889634f;
    #pragma unroll
    for (int n = 0; n < NST; ++n)
        A2[n] = -__expf(Alog[d*NST + n]) * LOG2E;
    a1 = A2[0];
    bool ok = true;
    #pragma unroll
    for (int n = 0; n < NST; ++n) {
        float e = a1 * (float)(n+1);
        ok = ok && (fabsf(A2[n] - e) <= 1e-5f*fabsf(e) + 1e-7f);
    }
    return __all_sync(0xffffffffu, ok);
}

// ---------------- pass 0: per-(b,l) projections ----------------
// One warp per 4 rows. Row outputs: dtsum = dt_raw + dt_snr_shift,
// B_eff[16] = B * (1-alpha + alpha*(gf + (1-gf)*sigmoid(snr_mod))), C[16].
__global__ __launch_bounds__(256) void k_row(
    const float* __restrict__ x,  const float* __restrict__ snr,
    const float* __restrict__ xw, const float* __restrict__ sw,
    const float* __restrict__ sb, const float* __restrict__ alpha_p,
    const float* __restrict__ gf_p)
{
    const int lane = threadIdx.x & 31;
    const int warp = (blockIdx.x * blockDim.x + threadIdx.x) >> 5;   // 0..2047
    const float alpha = *alpha_p;
    const float gf    = *gf_p;
    const float4* X4 = reinterpret_cast<const float4*>(x);
    const float4* W4 = reinterpret_cast<const float4*>(xw);

    for (int i = 0; i < 4; ++i) {
        const int r = warp*4 + i;                                    // 0..8191
        float acc[33];
        #pragma unroll
        for (int p = 0; p < 33; ++p) acc[p] = 0.f;

        #pragma unroll
        for (int kb = 0; kb < 4; ++kb) {
            int k4 = kb*32 + lane;                 // 128 float4 per row
            float4 xv = X4[(size_t)r*128 + k4];
            #pragma unroll
            for (int p = 0; p < 33; ++p) {
                float4 wv = W4[(size_t)p*128 + k4];
                acc[p] = fmaf(xv.x, wv.x, acc[p]);
                acc[p] = fmaf(xv.y, wv.y, acc[p]);
                acc[p] = fmaf(xv.z, wv.z, acc[p]);
                acc[p] = fmaf(xv.w, wv.w, acc[p]);
            }
        }
        #pragma unroll
        for (int p = 0; p < 33; ++p) {
            float v = acc[p];
            v += __shfl_xor_sync(0xffffffffu, v, 16);
            v += __shfl_xor_sync(0xffffffffu, v, 8);
            v += __shfl_xor_sync(0xffffffffu, v, 4);
            v += __shfl_xor_sync(0xffffffffu, v, 2);
            v += __shfl_xor_sync(0xffffffffu, v, 1);
            acc[p] = v;                            // full sum in all lanes
        }

        // snr projection: lane p (p<17) computes snr_mod[r, p]
        float s = 0.f;
        if (lane < 17) {
            s = sb[lane];
            const float* sr  = snr + (size_t)r*NMEL;
            const float* swr = sw  + (size_t)lane*NMEL;
            #pragma unroll
            for (int m = 0; m < NMEL; ++m) s = fmaf(sr[m], swr[m], s);
        }
        float sig    = 1.f / (1.f + __expf(-s));
        float gate   = gf + (1.f - gf) * sig;
        float factor = 1.f - alpha + alpha * gate;   // valid in lanes 1..16
        float s0 = __shfl_sync(0xffffffffu, s, 0);

        float* row = g_row + (size_t)r*ROWW;
        #pragma unroll
        for (int n = 0; n < NST; ++n) {
            float f = __shfl_sync(0xffffffffu, factor, n+1);
            if (lane == 0) {
                row[4+n]  = acc[1+n] * f;
                row[20+n] = acc[17+n];
            }
        }
        if (lane == 0) {
            row[0] = acc[0] + s0;
            row[1] = 0.f; row[2] = 0.f; row[3] = 0.f;
            row[36] = 0.f; row[37] = 0.f; row[38] = 0.f; row[39] = 0.f;
        }
    }
}

// ---------------- pass 1: chunk-local scan ----------------
template<bool TRICK>
__device__ __forceinline__ void scan_chunk(
    const float* __restrict__ rowp, const float* __restrict__ xrow,
    float* __restrict__ orow, float* __restrict__ crow,
    float wd, float bd, float Dp, float a1, const float (&A2)[NST],
    float (&h)[NST], float &cum)
{
    #pragma unroll 2
    for (int t = 0; t < TCH; ++t) {
        const float4* r4 = reinterpret_cast<const float4*>(rowp);
        float dts = rowp[0];
        float4 B0=r4[1],B1=r4[2],B2=r4[3],B3=r4[4];
        float4 C0=r4[5],C1=r4[6],C2=r4[7],C3=r4[8];
        float Bv[16] = {B0.x,B0.y,B0.z,B0.w, B1.x,B1.y,B1.z,B1.w,
                        B2.x,B2.y,B2.z,B2.w, B3.x,B3.y,B3.z,B3.w};
        float Cv[16] = {C0.x,C0.y,C0.z,C0.w, C1.x,C1.y,C1.z,C1.w,
                        C2.x,C2.y,C2.z,C2.w, C3.x,C3.y,C3.z,C3.w};

        float z   = fmaf(dts, wd, bd);
        float del = softplusf(z);
        cum += del;
        *crow = cum;

        float xv = *xrow;
        float dx = del * xv;
        float y  = Dp * xv;

        if (TRICK) {
            float p  = fex2(a1 * del);   // dA_1
            float pw = p;
            #pragma unroll
            for (int n = 0; n < NST; ++n) {
                h[n] = fmaf(pw, h[n], dx * Bv[n]);
                y    = fmaf(h[n], Cv[n], y);
                pw  *= p;                // pw = p^(n+2) for next n
            }
        } else {
            #pragma unroll
            for (int n = 0; n < NST; ++n) {
                float dA = fex2(A2[n] * del);
                h[n] = fmaf(dA, h[n], dx * Bv[n]);
                y    = fmaf(h[n], Cv[n], y);
            }
        }
        *orow = y;
        rowp += ROWW; xrow += DDIM; orow += DDIM; crow += DDIM;
    }
}

__global__ __launch_bounds__(256) void k_scan(
    const float* __restrict__ x,   const float* __restrict__ Alog,
    const float* __restrict__ dtw, const float* __restrict__ dtb,
    const float* __restrict__ Dprm, float* __restrict__ out)
{
    int tid = blockIdx.x * blockDim.x + threadIdx.x;   // 0..65535
    int d = tid & (DDIM-1);
    int c = (tid >> 9) & (NCH-1);
    int b = tid >> 13;

    float A2[NST]; float a1;
    bool trick = load_A2(Alog, d, A2, a1);

    float wd = dtw[d], bd = dtb[d], Dp = Dprm[d];
    float h[NST];
    #pragma unroll
    for (int n = 0; n < NST; ++n) h[n] = 0.f;
    float cum = 0.f;

    size_t rbase = (size_t)b*LDIM + (size_t)c*TCH;
    const float* rowp = g_row + rbase*ROWW;
    const float* xrow = x     + rbase*DDIM + d;
    float*       orow = out   + rbase*DDIM + d;
    float*       crow = g_cum + rbase*DDIM + d;

    if (trick) scan_chunk<true >(rowp, xrow, orow, crow, wd, bd, Dp, a1, A2, h, cum);
    else       scan_chunk<false>(rowp, xrow, orow, crow, wd, bd, Dp, a1, A2, h, cum);

    float* he = g_hend + ((size_t)(b*NCH + c)*NST)*DDIM + d;
    #pragma unroll
    for (int n = 0; n < NST; ++n) he[(size_t)n*DDIM] = h[n];
}

// ---------------- pass 2: sequential chunk combine ----------------
// h_true_in(c+1) = exp(A * cum_end(c)) * h_true_in(c) + h_local_end(c)
__global__ __launch_bounds__(256) void k_comb(const float* __restrict__ Alog)
{
    int tid = blockIdx.x * blockDim.x + threadIdx.x;   // 0..4095
    int d = tid & (DDIM-1);
    int b = tid >> 9;

    float A2[NST]; float a1;
    bool trick = load_A2(Alog, d, A2, a1);

    float h[NST];
    #pragma unroll
    for (int n = 0; n < NST; ++n) h[n] = 0.f;

    for (int c = 0; c < NCH; ++c) {
        size_t base = ((size_t)(b*NCH + c)*NST)*DDIM + d;
        #pragma unroll
        for (int n = 0; n < NST; ++n) g_hin[base + (size_t)n*DDIM] = h[n];

        float cend = g_cum[((size_t)b*LDIM + (size_t)c*TCH + TCH-1)*DDIM + d];
        if (trick) {
            float q  = fex2(a1 * cend);
            float pw = q;
            #pragma unroll
            for (int n = 0; n < NST; ++n) {
                h[n] = fmaf(pw, h[n], g_hend[base + (size_t)n*DDIM]);
                pw  *= q;
            }
        } else {
            #pragma unroll
            for (int n = 0; n < NST; ++n)
                h[n] = fmaf(fex2(A2[n]*cend), h[n], g_hend[base + (size_t)n*DDIM]);
        }
    }
}

// ---------------- pass 3: add cross-chunk correction ----------------
// y_true(l) = y_local(l) + sum_n exp(A_n * cum(l)) * h_in_n * C_n(l)
// cum is monotone increasing and A < 0, so once the correction is negligible
// for all lanes of the warp, break out of the chunk.
template<bool TRICK>
__device__ __forceinline__ void fix_chunk(
    const float* __restrict__ rowp, float* __restrict__ orow,
    const float* __restrict__ crow,
    float a1, float amax, const float (&A2)[NST],
    const float (&hin)[NST], float hsum)
{
    for (int t = 0; t < TCH; ++t) {
        float cum = crow[0];
        float e1  = fex2(amax * cum);
        bool live = (e1 * hsum > 1e-8f);
        if (!__any_sync(0xffffffffu, live)) return;
        if (live) {
            const float4* r4 = reinterpret_cast<const float4*>(rowp);
            float4 C0=r4[5],C1=r4[6],C2=r4[7],C3=r4[8];
            float Cv[16] = {C0.x,C0.y,C0.z,C0.w, C1.x,C1.y,C1.z,C1.w,
                            C2.x,C2.y,C2.z,C2.w, C3.x,C3.y,C3.z,C3.w};
            float corr = 0.f;
            if (TRICK) {
                float q  = fex2(a1 * cum);
                float pw = q;
                #pragma unroll
                for (int n = 0; n < NST; ++n) {
                    corr = fmaf(pw * hin[n], Cv[n], corr);
                    pw  *= q;
                }
            } else {
                #pragma unroll
                for (int n = 0; n < NST; ++n)
                    corr = fmaf(fex2(A2[n]*cum) * hin[n], Cv[n], corr);
            }
            orow[0] += corr;
        }
        rowp += ROWW; orow += DDIM; crow += DDIM;
    }
}

__global__ __launch_bounds__(256) void k_fix(const float* __restrict__ Alog,
                                             float* __restrict__ out)
{
    int tid = blockIdx.x * blockDim.x + threadIdx.x;
    int d = tid & (DDIM-1);
    int c = (tid >> 9) & (NCH-1);
    int b = tid >> 13;
    if (c == 0) return;   // warp-uniform: h_in = 0, no correction

    float A2[NST]; float a1;
    bool trick = load_A2(Alog, d, A2, a1);
    float amax = A2[0];
    #pragma unroll
    for (int n = 1; n < NST; ++n) amax = fmaxf(amax, A2[n]);

    float hin[NST];
    size_t hb = ((size_t)(b*NCH + c)*NST)*DDIM + d;
    float hsum = 0.f;
    #pragma unroll
    for (int n = 0; n < NST; ++n) {
        hin[n] = g_hin[hb + (size_t)n*DDIM];
        hsum  += fabsf(hin[n]);
    }

    size_t rbase = (size_t)b*LDIM + (size_t)c*TCH;
    const float* rowp = g_row + rbase*ROWW;
    float*       orow = out   + rbase*DDIM + d;
    const float* crow = g_cum + rbase*DDIM + d;

    if (trick) fix_chunk<true >(rowp, orow, crow, a1, amax, A2, hin, hsum);
    else       fix_chunk<false>(rowp, orow, crow, a1, amax, A2, hin, hsum);
}

extern "C" void kernel_launch(void* const* d_in, const int* in_sizes, int n_in,
                              void* d_out, int out_size)
{
    const float* x    = (const float*)d_in[0];
    const float* snr  = (const float*)d_in[1];
    const float* xw   = (const float*)d_in[2];
    const float* sw   = (const float*)d_in[3];
    const float* sb   = (const float*)d_in[4];
    const float* dtw  = (const float*)d_in[5];
    const float* dtb  = (const float*)d_in[6];
    const float* Alog = (const float*)d_in[7];
    const float* Dp   = (const float*)d_in[8];
    const float* al   = (const float*)d_in[9];
    const float* gf   = (const float*)d_in[10];
    float* out = (float*)d_out;

    k_row <<<256, 256>>>(x, snr, xw, sw, sb, al, gf);
    k_scan<<<256, 256>>>(x, Alog, dtw, dtb, Dp, out);
    k_comb<<<16, 256>>>(Alog);
    k_fix <<<256, 256>>>(Alog, out);
}

// round 2
// speedup vs baseline: 1.1322x; 1.1322x over previous
#include <cuda_runtime.h>
#include <math.h>

#define BDIM 8
#define LDIM 1024
#define DDIM 512
#define NST  16
#define NMEL 40
#define NCH  32
#define TCH  (LDIM/NCH)   // 32
#define ROWW 40           // [0]=dtsum, [4..19]=B_eff, [20..35]=C

// Scratch (device globals; allocations are forbidden)
__device__ float g_row [BDIM*LDIM*ROWW];            // 1.31 MB
__device__ float g_hend[BDIM*NCH*NST*DDIM];         // 8 MB  chunk-local final states
__device__ float g_hin [BDIM*NCH*NST*DDIM];         // 8 MB  true incoming states
__device__ float g_cend[BDIM*NCH*DDIM];             // 0.5 MB chunk-local sum of delta

__device__ __forceinline__ float fex2(float x){
    float r; asm("ex2.approx.f32 %0,%1;" : "=f"(r) : "f"(x)); return r;
}
__device__ __forceinline__ float softplusf(float z){
    return (z > 15.f) ? z : __logf(1.f + __expf(z));
}

// A2[n] = -exp(A_log[d,n]) * log2(e); detect A2[n] == (n+1)*A2[0]
// (true for this dataset) -> dA_n = p^(n+1) with one ex2.
__device__ __forceinline__ bool load_A2(const float* __restrict__ Alog, int d,
                                        float (&A2)[NST], float &a1)
{
    const float LOG2E = 1.4426950408889634f;
    #pragma unroll
    for (int n = 0; n < NST; ++n)
        A2[n] = -__expf(Alog[d*NST + n]) * LOG2E;
    a1 = A2[0];
    bool ok = true;
    #pragma unroll
    for (int n = 0; n < NST; ++n) {
        float e = a1 * (float)(n+1);
        ok = ok && (fabsf(A2[n] - e) <= 1e-5f*fabsf(e) + 1e-7f);
    }
    return __all_sync(0xffffffffu, ok);
}

// ---------------- pass 0: per-(b,l) projections ----------------
__global__ __launch_bounds__(256) void k_row(
    const float* __restrict__ x,  const float* __restrict__ snr,
    const float* __restrict__ xw, const float* __restrict__ sw,
    const float* __restrict__ sb, const float* __restrict__ alpha_p,
    const float* __restrict__ gf_p)
{
    __shared__ float s_swT[NMEL*17];   // transposed: [m][p]
    __shared__ float s_sb[17];
    for (int i = threadIdx.x; i < 17*NMEL; i += 256) {
        int p = i / NMEL, m = i % NMEL;
        s_swT[m*17 + p] = sw[i];
    }
    if (threadIdx.x < 17) s_sb[threadIdx.x] = sb[threadIdx.x];
    __syncthreads();

    const int lane = threadIdx.x & 31;
    const int warp = (blockIdx.x * blockDim.x + threadIdx.x) >> 5;   // 0..2047
    const float alpha = *alpha_p;
    const float gf    = *gf_p;
    const float4* X4 = reinterpret_cast<const float4*>(x);
    const float4* W4 = reinterpret_cast<const float4*>(xw);

    for (int i = 0; i < 4; ++i) {
        const int r = warp*4 + i;                                    // 0..8191
        float acc[33];
        #pragma unroll
        for (int p = 0; p < 33; ++p) acc[p] = 0.f;

        #pragma unroll
        for (int kb = 0; kb < 4; ++kb) {
            int k4 = kb*32 + lane;
            float4 xv = X4[(size_t)r*128 + k4];
            #pragma unroll
            for (int p = 0; p < 33; ++p) {
                float4 wv = W4[(size_t)p*128 + k4];
                acc[p] = fmaf(xv.x, wv.x, acc[p]);
                acc[p] = fmaf(xv.y, wv.y, acc[p]);
                acc[p] = fmaf(xv.z, wv.z, acc[p]);
                acc[p] = fmaf(xv.w, wv.w, acc[p]);
            }
        }
        #pragma unroll
        for (int p = 0; p < 33; ++p) {
            float v = acc[p];
            v += __shfl_xor_sync(0xffffffffu, v, 16);
            v += __shfl_xor_sync(0xffffffffu, v, 8);
            v += __shfl_xor_sync(0xffffffffu, v, 4);
            v += __shfl_xor_sync(0xffffffffu, v, 2);
            v += __shfl_xor_sync(0xffffffffu, v, 1);
            acc[p] = v;
        }

        // snr projection from smem (conflict-free): lane p < 17 owns output p
        float s = 0.f;
        if (lane < 17) {
            s = s_sb[lane];
            const float* sr = snr + (size_t)r*NMEL;
            #pragma unroll
            for (int m = 0; m < NMEL; ++m)
                s = fmaf(sr[m], s_swT[m*17 + lane], s);
        }
        float sig    = 1.f / (1.f + __expf(-s));
        float gate   = gf + (1.f - gf) * sig;
        float factor = 1.f - alpha + alpha * gate;     // lanes 1..16
        float s0 = __shfl_sync(0xffffffffu, s, 0);

        float* row = g_row + (size_t)r*ROWW;
        #pragma unroll
        for (int n = 0; n < NST; ++n) {
            float f = __shfl_sync(0xffffffffu, factor, n+1);
            if (lane == 0) {
                row[4+n]  = acc[1+n] * f;
                row[20+n] = acc[17+n];
            }
        }
        if (lane == 0) {
            row[0] = acc[0] + s0;
            row[1] = 0.f; row[2] = 0.f; row[3] = 0.f;
            row[36] = 0.f; row[37] = 0.f; row[38] = 0.f; row[39] = 0.f;
        }
    }
}

// ---------------- pass 1: chunk-local scan (states only) ----------------
template<bool TRICK>
__device__ __forceinline__ void scanA_chunk(
    const float* __restrict__ rowp, const float* __restrict__ xrow,
    float wd, float bd, float a1, const float (&A2)[NST],
    float (&h)[NST], float &cum)
{
    #pragma unroll 2
    for (int t = 0; t < TCH; ++t) {
        const float4* r4 = reinterpret_cast<const float4*>(rowp);
        float dts = rowp[0];
        float4 B0=r4[1],B1=r4[2],B2=r4[3],B3=r4[4];
        float Bv[16] = {B0.x,B0.y,B0.z,B0.w, B1.x,B1.y,B1.z,B1.w,
                        B2.x,B2.y,B2.z,B2.w, B3.x,B3.y,B3.z,B3.w};
        float del = softplusf(fmaf(dts, wd, bd));
        cum += del;
        float dx = del * (*xrow);

        if (TRICK) {
            float p  = fex2(a1 * del);
            float pw = p;
            #pragma unroll
            for (int n = 0; n < NST; ++n) {
                h[n] = fmaf(pw, h[n], dx * Bv[n]);
                pw  *= p;
            }
        } else {
            #pragma unroll
            for (int n = 0; n < NST; ++n)
                h[n] = fmaf(fex2(A2[n]*del), h[n], dx * Bv[n]);
        }
        rowp += ROWW; xrow += DDIM;
    }
}

__global__ __launch_bounds__(256) void k_scanA(
    const float* __restrict__ x,   const float* __restrict__ Alog,
    const float* __restrict__ dtw, const float* __restrict__ dtb)
{
    int tid = blockIdx.x * blockDim.x + threadIdx.x;   // 0..131071
    int d = tid & (DDIM-1);
    int c = (tid >> 9) & (NCH-1);
    int b = tid >> 14;

    float A2[NST]; float a1;
    bool trick = load_A2(Alog, d, A2, a1);

    float wd = dtw[d], bd = dtb[d];
    float h[NST];
    #pragma unroll
    for (int n = 0; n < NST; ++n) h[n] = 0.f;
    float cum = 0.f;

    size_t rbase = (size_t)b*LDIM + (size_t)c*TCH;
    const float* rowp = g_row + rbase*ROWW;
    const float* xrow = x     + rbase*DDIM + d;

    if (trick) scanA_chunk<true >(rowp, xrow, wd, bd, a1, A2, h, cum);
    else       scanA_chunk<false>(rowp, xrow, wd, bd, a1, A2, h, cum);

    size_t hb = ((size_t)(b*NCH + c)*NST)*DDIM + d;
    #pragma unroll
    for (int n = 0; n < NST; ++n) g_hend[hb + (size_t)n*DDIM] = h[n];
    g_cend[((size_t)b*NCH + c)*DDIM + d] = cum;
}

// ---------------- pass 2: cross-chunk combine, one thread per (b,d,n) ----------------
__global__ __launch_bounds__(256) void k_comb(const float* __restrict__ Alog)
{
    int tid = blockIdx.x * blockDim.x + threadIdx.x;   // 0..65535
    int d = tid & (DDIM-1);
    int n = (tid >> 9) & (NST-1);
    int b = tid >> 13;

    const float LOG2E = 1.4426950408889634f;
    float a = -__expf(Alog[d*NST + n]) * LOG2E;

    float h = 0.f;
    for (int c = 0; c < NCH; ++c) {
        size_t hb = ((size_t)(b*NCH + c)*NST + n)*DDIM + d;
        g_hin[hb] = h;
        float ce = g_cend[((size_t)b*NCH + c)*DDIM + d];
        h = fmaf(fex2(a * ce), h, g_hend[hb]);
    }
}

// ---------------- pass 3: full scan with true incoming state ----------------
template<bool TRICK>
__device__ __forceinline__ void scanB_chunk(
    const float* __restrict__ rowp, const float* __restrict__ xrow,
    float* __restrict__ orow,
    float wd, float bd, float Dp, float a1, const float (&A2)[NST],
    float (&h)[NST])
{
    #pragma unroll 2
    for (int t = 0; t < TCH; ++t) {
        const float4* r4 = reinterpret_cast<const float4*>(rowp);
        float dts = rowp[0];
        float4 B0=r4[1],B1=r4[2],B2=r4[3],B3=r4[4];
        float4 C0=r4[5],C1=r4[6],C2=r4[7],C3=r4[8];
        float Bv[16] = {B0.x,B0.y,B0.z,B0.w, B1.x,B1.y,B1.z,B1.w,
                        B2.x,B2.y,B2.z,B2.w, B3.x,B3.y,B3.z,B3.w};
        float Cv[16] = {C0.x,C0.y,C0.z,C0.w, C1.x,C1.y,C1.z,C1.w,
                        C2.x,C2.y,C2.z,C2.w, C3.x,C3.y,C3.z,C3.w};

        float del = softplusf(fmaf(dts, wd, bd));
        float xv  = *xrow;
        float dx  = del * xv;
        float y   = Dp * xv;

        if (TRICK) {
            float p  = fex2(a1 * del);
            float pw = p;
            #pragma unroll
            for (int n = 0; n < NST; ++n) {
                h[n] = fmaf(pw, h[n], dx * Bv[n]);
                y    = fmaf(h[n], Cv[n], y);
                pw  *= p;
            }
        } else {
            #pragma unroll
            for (int n = 0; n < NST; ++n) {
                h[n] = fmaf(fex2(A2[n]*del), h[n], dx * Bv[n]);
                y    = fmaf(h[n], Cv[n], y);
            }
        }
        *orow = y;
        rowp += ROWW; xrow += DDIM; orow += DDIM;
    }
}

__global__ __launch_bounds__(256) void k_scanB(
    const float* __restrict__ x,   const float* __restrict__ Alog,
    const float* __restrict__ dtw, const float* __restrict__ dtb,
    const float* __restrict__ Dprm, float* __restrict__ out)
{
    int tid = blockIdx.x * blockDim.x + threadIdx.x;   // 0..131071
    int d = tid & (DDIM-1);
    int c = (tid >> 9) & (NCH-1);
    int b = tid >> 14;

    float A2[NST]; float a1;
    bool trick = load_A2(Alog, d, A2, a1);

    float wd = dtw[d], bd = dtb[d], Dp = Dprm[d];

    float h[NST];
    size_t hb = ((size_t)(b*NCH + c)*NST)*DDIM + d;
    #pragma unroll
    for (int n = 0; n < NST; ++n) h[n] = g_hin[hb + (size_t)n*DDIM];

    size_t rbase = (size_t)b*LDIM + (size_t)c*TCH;
    const float* rowp = g_row + rbase*ROWW;
    const float* xrow = x     + rbase*DDIM + d;
    float*       orow = out   + rbase*DDIM + d;

    if (trick) scanB_chunk<true >(rowp, xrow, orow, wd, bd, Dp, a1, A2, h);
    else       scanB_chunk<false>(rowp, xrow, orow, wd, bd, Dp, a1, A2, h);
}

extern "C" void kernel_launch(void* const* d_in, const int* in_sizes, int n_in,
                              void* d_out, int out_size)
{
    const float* x    = (const float*)d_in[0];
    const float* snr  = (const float*)d_in[1];
    const float* xw   = (const float*)d_in[2];
    const float* sw   = (const float*)d_in[3];
    const float* sb   = (const float*)d_in[4];
    const float* dtw  = (const float*)d_in[5];
    const float* dtb  = (const float*)d_in[6];
    const float* Alog = (const float*)d_in[7];
    const float* Dp   = (const float*)d_in[8];
    const float* al   = (const float*)d_in[9];
    const float* gf   = (const float*)d_in[10];
    float* out = (float*)d_out;

    k_row  <<<256, 256>>>(x, snr, xw, sw, sb, al, gf);
    k_scanA<<<512, 256>>>(x, Alog, dtw, dtb);
    k_comb <<<256, 256>>>(Alog);
    k_scanB<<<512, 256>>>(x, Alog, dtw, dtb, Dp, out);
}

// round 4
// speedup vs baseline: 1.4543x; 1.2844x over previous
#include <cuda_runtime.h>
#include <math.h>

#define BDIM 8
#define LDIM 1024
#define DDIM 512
#define NST  16
#define NMEL 40
#define NCH  32
#define TCH  (LDIM/NCH)   // 32
#define ROWW 40           // [0]=dtsum, [4..19]=B_eff, [20..35]=C

typedef unsigned long long u64;

// Scratch (device globals; allocations are forbidden)
__device__ float g_row [BDIM*LDIM*ROWW];            // 1.31 MB
__device__ float g_hend[BDIM*NCH*NST*DDIM];         // 8 MB
__device__ float g_hin [BDIM*NCH*NST*DDIM];         // 8 MB
__device__ float g_cend[BDIM*NCH*DDIM];             // 0.5 MB

__device__ __forceinline__ float fex2(float x){
    float r; asm("ex2.approx.f32 %0,%1;" : "=f"(r) : "f"(x)); return r;
}
__device__ __forceinline__ float softplusf(float z){
    return (z > 15.f) ? z : __logf(1.f + __expf(z));
}
__device__ __forceinline__ u64 pack2(float lo, float hi){
    u64 r; asm("mov.b64 %0,{%1,%2};" : "=l"(r) : "f"(lo), "f"(hi)); return r;
}
__device__ __forceinline__ void unpack2(u64 v, float &lo, float &hi){
    asm("mov.b64 {%0,%1},%2;" : "=f"(lo), "=f"(hi) : "l"(v));
}
__device__ __forceinline__ u64 fma2(u64 a, u64 b, u64 c){
    u64 d; asm("fma.rn.f32x2 %0,%1,%2,%3;" : "=l"(d) : "l"(a), "l"(b), "l"(c)); return d;
}
__device__ __forceinline__ u64 mul2(u64 a, u64 b){
    u64 d; asm("mul.rn.f32x2 %0,%1,%2;" : "=l"(d) : "l"(a), "l"(b)); return d;
}

// A2[n] = -exp(A_log[d,n]) * log2(e); detect A2[n] == (n+1)*A2[0]
__device__ __forceinline__ bool load_A2(const float* __restrict__ Alog, int d,
                                        float (&A2)[NST], float &a1)
{
    const float LOG2E = 1.4426950408889634f;
    #pragma unroll
    for (int n = 0; n < NST; ++n)
        A2[n] = -__expf(Alog[d*NST + n]) * LOG2E;
    a1 = A2[0];
    bool ok = true;
    #pragma unroll
    for (int n = 0; n < NST; ++n) {
        float e = a1 * (float)(n+1);
        ok = ok && (fabsf(A2[n] - e) <= 1e-5f*fabsf(e) + 1e-7f);
    }
    return __all_sync(0xffffffffu, ok);
}

// Build pw[k] = (p^(2k+1), p^(2k+2)) with two depth-4 chains.
__device__ __forceinline__ void build_pw(float p, u64 (&pw)[8])
{
    float p2s = p * p;
    pw[0] = pack2(p, p2s);
    u64 s2 = pack2(p2s, p2s);
    u64 s4 = mul2(s2, s2);
    pw[1] = mul2(pw[0], s2);
    pw[2] = mul2(pw[0], s4);
    pw[3] = mul2(pw[1], s4);
    pw[4] = mul2(pw[2], s4);
    pw[5] = mul2(pw[3], s4);
    pw[6] = mul2(pw[4], s4);
    pw[7] = mul2(pw[5], s4);
}

// ---------------- pass 0: per-(b,l) projections ----------------
__global__ __launch_bounds__(256) void k_row(
    const float* __restrict__ x,  const float* __restrict__ snr,
    const float* __restrict__ xw, const float* __restrict__ sw,
    const float* __restrict__ sb, const float* __restrict__ alpha_p,
    const float* __restrict__ gf_p)
{
    __shared__ float s_swT[NMEL*17];
    __shared__ float s_sb[17];
    for (int i = threadIdx.x; i < 17*NMEL; i += 256) {
        int p = i / NMEL, m = i % NMEL;
        s_swT[m*17 + p] = sw[i];
    }
    if (threadIdx.x < 17) s_sb[threadIdx.x] = sb[threadIdx.x];
    __syncthreads();

    const int lane = threadIdx.x & 31;
    const int warp = (blockIdx.x * blockDim.x + threadIdx.x) >> 5;   // 0..2047
    const float alpha = *alpha_p;
    const float gf    = *gf_p;
    const ulonglong2* X2 = reinterpret_cast<const ulonglong2*>(x);
    const ulonglong2* W2 = reinterpret_cast<const ulonglong2*>(xw);

    for (int i = 0; i < 4; ++i) {
        const int r = warp*4 + i;                                    // 0..8191
        u64 acc2[33];
        #pragma unroll
        for (int p = 0; p < 33; ++p) acc2[p] = 0ull;

        #pragma unroll
        for (int kb = 0; kb < 4; ++kb) {
            int k4 = kb*32 + lane;                 // 128 float4 per row
            ulonglong2 xv = X2[(size_t)r*128 + k4];
            #pragma unroll
            for (int p = 0; p < 33; ++p) {
                ulonglong2 wv = W2[(size_t)p*128 + k4];
                acc2[p] = fma2(xv.x, wv.x, acc2[p]);
                acc2[p] = fma2(xv.y, wv.y, acc2[p]);
            }
        }
        float acc[33];
        #pragma unroll
        for (int p = 0; p < 33; ++p) {
            float lo, hi; unpack2(acc2[p], lo, hi);
            float v = lo + hi;
            v += __shfl_xor_sync(0xffffffffu, v, 16);
            v += __shfl_xor_sync(0xffffffffu, v, 8);
            v += __shfl_xor_sync(0xffffffffu, v, 4);
            v += __shfl_xor_sync(0xffffffffu, v, 2);
            v += __shfl_xor_sync(0xffffffffu, v, 1);
            acc[p] = v;
        }

        float s = 0.f;
        if (lane < 17) {
            s = s_sb[lane];
            const float* sr = snr + (size_t)r*NMEL;
            #pragma unroll
            for (int m = 0; m < NMEL; ++m)
                s = fmaf(sr[m], s_swT[m*17 + lane], s);
        }
        float sig    = 1.f / (1.f + __expf(-s));
        float gate   = gf + (1.f - gf) * sig;
        float factor = 1.f - alpha + alpha * gate;     // lanes 1..16
        float s0 = __shfl_sync(0xffffffffu, s, 0);

        float* row = g_row + (size_t)r*ROWW;
        #pragma unroll
        for (int n = 0; n < NST; ++n) {
            float f = __shfl_sync(0xffffffffu, factor, n+1);
            if (lane == 0) {
                row[4+n]  = acc[1+n] * f;
                row[20+n] = acc[17+n];
            }
        }
        if (lane == 0) row[0] = acc[0] + s0;
    }
}

// ---------------- pass 1: chunk-local scan (states only) ----------------
__global__ __launch_bounds__(256) void k_scanA(
    const float* __restrict__ x,   const float* __restrict__ Alog,
    const float* __restrict__ dtw, const float* __restrict__ dtb)
{
    __shared__ float s_row[TCH*ROWW];   // 5 KB
    const int bid = blockIdx.x;         // 0..511
    const int b  = bid >> 6;
    const int c  = (bid >> 1) & (NCH-1);
    const int dh = bid & 1;
    const int d  = dh*256 + threadIdx.x;

    size_t rbase = (size_t)b*LDIM + (size_t)c*TCH;
    {
        const float4* g4 = reinterpret_cast<const float4*>(g_row + rbase*ROWW);
        float4* s4p = reinterpret_cast<float4*>(s_row);
        for (int i = threadIdx.x; i < TCH*ROWW/4; i += 256) s4p[i] = g4[i];
    }
    __syncthreads();

    float A2[NST]; float a1;
    bool trick = load_A2(Alog, d, A2, a1);
    const float wd = dtw[d], bd = dtb[d];

    const float* xrow = x + rbase*DDIM + d;
    float cum = 0.f;
    u64 h2[8];
    #pragma unroll
    for (int k = 0; k < 8; ++k) h2[k] = 0ull;

    if (trick) {
        #pragma unroll 2
        for (int t = 0; t < TCH; ++t) {
            const float* srow = s_row + t*ROWW;
            float dts = srow[0];
            float del = softplusf(fmaf(dts, wd, bd));
            cum += del;
            float dx = del * xrow[(size_t)t*DDIM];
            u64 dx2 = pack2(dx, dx);
            u64 pw[8]; build_pw(fex2(a1*del), pw);

            ulonglong2 Bq0 = *reinterpret_cast<const ulonglong2*>(srow+4);
            ulonglong2 Bq1 = *reinterpret_cast<const ulonglong2*>(srow+8);
            ulonglong2 Bq2 = *reinterpret_cast<const ulonglong2*>(srow+12);
            ulonglong2 Bq3 = *reinterpret_cast<const ulonglong2*>(srow+16);
            u64 B2[8] = {Bq0.x, Bq0.y, Bq1.x, Bq1.y, Bq2.x, Bq2.y, Bq3.x, Bq3.y};
            #pragma unroll
            for (int k = 0; k < 8; ++k)
                h2[k] = fma2(pw[k], h2[k], mul2(dx2, B2[k]));
        }
    } else {
        float h[NST];
        #pragma unroll
        for (int n = 0; n < NST; ++n) h[n] = 0.f;
        for (int t = 0; t < TCH; ++t) {
            const float* srow = s_row + t*ROWW;
            float del = softplusf(fmaf(srow[0], wd, bd));
            cum += del;
            float dx = del * xrow[(size_t)t*DDIM];
            #pragma unroll
            for (int n = 0; n < NST; ++n)
                h[n] = fmaf(fex2(A2[n]*del), h[n], dx * srow[4+n]);
        }
        #pragma unroll
        for (int k = 0; k < 8; ++k) h2[k] = pack2(h[2*k], h[2*k+1]);
    }

    size_t hb = ((size_t)(b*NCH + c)*NST)*DDIM + d;
    #pragma unroll
    for (int k = 0; k < 8; ++k) {
        float lo, hi; unpack2(h2[k], lo, hi);
        g_hend[hb + (size_t)(2*k)*DDIM]   = lo;
        g_hend[hb + (size_t)(2*k+1)*DDIM] = hi;
    }
    g_cend[((size_t)b*NCH + c)*DDIM + d] = cum;
}

// ---------------- pass 2: cross-chunk combine, one thread per (b,d,n) ----------------
__global__ __launch_bounds__(256) void k_comb(const float* __restrict__ Alog)
{
    int tid = blockIdx.x * blockDim.x + threadIdx.x;   // 0..65535
    int d = tid & (DDIM-1);
    int n = (tid >> 9) & (NST-1);
    int b = tid >> 13;

    const float LOG2E = 1.4426950408889634f;
    float a = -__expf(Alog[d*NST + n]) * LOG2E;

    float h = 0.f;
    for (int c = 0; c < NCH; ++c) {
        size_t hb = ((size_t)(b*NCH + c)*NST + n)*DDIM + d;
        g_hin[hb] = h;
        float ce = g_cend[((size_t)b*NCH + c)*DDIM + d];
        h = fmaf(fex2(a * ce), h, g_hend[hb]);
    }
}

// ---------------- pass 3: full scan with true incoming state ----------------
__global__ __launch_bounds__(256) void k_scanB(
    const float* __restrict__ x,   const float* __restrict__ Alog,
    const float* __restrict__ dtw, const float* __restrict__ dtb,
    const float* __restrict__ Dprm, float* __restrict__ out)
{
    __shared__ float s_row[TCH*ROWW];
    const int bid = blockIdx.x;
    const int b  = bid >> 6;
    const int c  = (bid >> 1) & (NCH-1);
    const int dh = bid & 1;
    const int d  = dh*256 + threadIdx.x;

    size_t rbase = (size_t)b*LDIM + (size_t)c*TCH;
    {
        const float4* g4 = reinterpret_cast<const float4*>(g_row + rbase*ROWW);
        float4* s4p = reinterpret_cast<float4*>(s_row);
        for (int i = threadIdx.x; i < TCH*ROWW/4; i += 256) s4p[i] = g4[i];
    }
    __syncthreads();

    float A2[NST]; float a1;
    bool trick = load_A2(Alog, d, A2, a1);
    const float wd = dtw[d], bd = dtb[d], Dp = Dprm[d];

    u64 h2[8];
    size_t hb = ((size_t)(b*NCH + c)*NST)*DDIM + d;
    #pragma unroll
    for (int k = 0; k < 8; ++k)
        h2[k] = pack2(g_hin[hb + (size_t)(2*k)*DDIM],
                      g_hin[hb + (size_t)(2*k+1)*DDIM]);

    const float* xrow = x   + rbase*DDIM + d;
    float*       orow = out + rbase*DDIM + d;

    if (trick) {
        #pragma unroll 2
        for (int t = 0; t < TCH; ++t) {
            const float* srow = s_row + t*ROWW;
            float dts = srow[0];
            float del = softplusf(fmaf(dts, wd, bd));
            float xv  = xrow[(size_t)t*DDIM];
            float dx  = del * xv;
            u64 dx2 = pack2(dx, dx);
            u64 pw[8]; build_pw(fex2(a1*del), pw);

            ulonglong2 Bq0 = *reinterpret_cast<const ulonglong2*>(srow+4);
            ulonglong2 Bq1 = *reinterpret_cast<const ulonglong2*>(srow+8);
            ulonglong2 Bq2 = *reinterpret_cast<const ulonglong2*>(srow+12);
            ulonglong2 Bq3 = *reinterpret_cast<const ulonglong2*>(srow+16);
            ulonglong2 Cq0 = *reinterpret_cast<const ulonglong2*>(srow+20);
            ulonglong2 Cq1 = *reinterpret_cast<const ulonglong2*>(srow+24);
            ulonglong2 Cq2 = *reinterpret_cast<const ulonglong2*>(srow+28);
            ulonglong2 Cq3 = *reinterpret_cast<const ulonglong2*>(srow+32);
            u64 B2[8] = {Bq0.x, Bq0.y, Bq1.x, Bq1.y, Bq2.x, Bq2.y, Bq3.x, Bq3.y};
            u64 C2[8] = {Cq0.x, Cq0.y, Cq1.x, Cq1.y, Cq2.x, Cq2.y, Cq3.x, Cq3.y};

            u64 y2 = pack2(Dp * xv, 0.f);
            #pragma unroll
            for (int k = 0; k < 8; ++k) {
                h2[k] = fma2(pw[k], h2[k], mul2(dx2, B2[k]));
                y2    = fma2(h2[k], C2[k], y2);
            }
            float ylo, yhi; unpack2(y2, ylo, yhi);
            orow[(size_t)t*DDIM] = ylo + yhi;
        }
    } else {
        float h[NST];
        #pragma unroll
        for (int k = 0; k < 8; ++k) unpack2(h2[k], h[2*k], h[2*k+1]);
        for (int t = 0; t < TCH; ++t) {
            const float* srow = s_row + t*ROWW;
            float del = softplusf(fmaf(srow[0], wd, bd));
            float xv  = xrow[(size_t)t*DDIM];
            float dx  = del * xv;
            float y   = Dp * xv;
            #pragma unroll
            for (int n = 0; n < NST; ++n) {
                h[n] = fmaf(fex2(A2[n]*del), h[n], dx * srow[4+n]);
                y    = fmaf(h[n], srow[20+n], y);
            }
            orow[(size_t)t*DDIM] = y;
        }
    }
}

extern "C" void kernel_launch(void* const* d_in, const int* in_sizes, int n_in,
                              void* d_out, int out_size)
{
    const float* x    = (const float*)d_in[0];
    const float* snr  = (const float*)d_in[1];
    const float* xw   = (const float*)d_in[2];
    const float* sw   = (const float*)d_in[3];
    const float* sb   = (const float*)d_in[4];
    const float* dtw  = (const float*)d_in[5];
    const float* dtb  = (const float*)d_in[6];
    const float* Alog = (const float*)d_in[7];
    const float* Dp   = (const float*)d_in[8];
    const float* al   = (const float*)d_in[9];
    const float* gf   = (const float*)d_in[10];
    float* out = (float*)d_out;

    k_row  <<<256, 256>>>(x, snr, xw, sw, sb, al, gf);
    k_scanA<<<512, 256>>>(x, Alog, dtw, dtb);
    k_comb <<<256, 256>>>(Alog);
    k_scanB<<<512, 256>>>(x, Alog, dtw, dtb, Dp, out);
}

// round 5
// speedup vs baseline: 2.4946x; 1.7154x over previous
#include <cuda_runtime.h>
#include <math.h>

#define BDIM 8
#define LDIM 1024
#define DDIM 512
#define NST  16
#define NMEL 40
#define NCH  32
#define TCH  (LDIM/NCH)   // 32
#define ROWW 40           // [0]=dtsum, [4..19]=B_eff, [20..35]=C

typedef unsigned long long u64;

// Scratch (device globals; allocations are forbidden)
__device__ float g_row [BDIM*LDIM*ROWW];            // 1.31 MB
__device__ float g_hend[BDIM*NCH*NST*DDIM];         // 8 MB
__device__ float g_hin [BDIM*NCH*NST*DDIM];         // 8 MB
__device__ float g_cend[BDIM*NCH*DDIM];             // 0.5 MB

__device__ __forceinline__ float fex2(float x){
    float r; asm("ex2.approx.f32 %0,%1;" : "=f"(r) : "f"(x)); return r;
}
__device__ __forceinline__ float softplusf(float z){
    return (z > 15.f) ? z : __logf(1.f + __expf(z));
}
__device__ __forceinline__ u64 pack2(float lo, float hi){
    u64 r; asm("mov.b64 %0,{%1,%2};" : "=l"(r) : "f"(lo), "f"(hi)); return r;
}
__device__ __forceinline__ void unpack2(u64 v, float &lo, float &hi){
    asm("mov.b64 {%0,%1},%2;" : "=f"(lo), "=f"(hi) : "l"(v));
}
__device__ __forceinline__ u64 fma2(u64 a, u64 b, u64 c){
    u64 d; asm("fma.rn.f32x2 %0,%1,%2,%3;" : "=l"(d) : "l"(a), "l"(b), "l"(c)); return d;
}
__device__ __forceinline__ u64 mul2(u64 a, u64 b){
    u64 d; asm("mul.rn.f32x2 %0,%1,%2;" : "=l"(d) : "l"(a), "l"(b)); return d;
}

// A2[n] = -exp(A_log[d,n]) * log2(e); detect A2[n] == (n+1)*A2[0]
__device__ __forceinline__ bool load_A2(const float* __restrict__ Alog, int d,
                                        float (&A2)[NST], float &a1)
{
    const float LOG2E = 1.4426950408889634f;
    #pragma unroll
    for (int n = 0; n < NST; ++n)
        A2[n] = -__expf(Alog[d*NST + n]) * LOG2E;
    a1 = A2[0];
    bool ok = true;
    #pragma unroll
    for (int n = 0; n < NST; ++n) {
        float e = a1 * (float)(n+1);
        ok = ok && (fabsf(A2[n] - e) <= 1e-5f*fabsf(e) + 1e-7f);
    }
    return __all_sync(0xffffffffu, ok);
}

// Build pw[k] = (p^(2k+1), p^(2k+2)) with two depth-4 chains.
__device__ __forceinline__ void build_pw(float p, u64 (&pw)[8])
{
    float p2s = p * p;
    pw[0] = pack2(p, p2s);
    u64 s2 = pack2(p2s, p2s);
    u64 s4 = mul2(s2, s2);
    pw[1] = mul2(pw[0], s2);
    pw[2] = mul2(pw[0], s4);
    pw[3] = mul2(pw[1], s4);
    pw[4] = mul2(pw[2], s4);
    pw[5] = mul2(pw[3], s4);
    pw[6] = mul2(pw[4], s4);
    pw[7] = mul2(pw[5], s4);
}

// ---------------- pass 0: per-(b,l) projections ----------------
// 8 lanes per row, 4 rows per warp. Lane owns a 64-elem k-slice, accumulates
// all 33 projection outputs in f32x2, reduces across 8 lanes (3 shfl levels),
// then lane i of each group finalizes outputs p = i, i+8, i+16, ...
__global__ __launch_bounds__(256) void k_row(
    const float* __restrict__ x,  const float* __restrict__ snr,
    const float* __restrict__ xw, const float* __restrict__ sw,
    const float* __restrict__ sb, const float* __restrict__ alpha_p,
    const float* __restrict__ gf_p)
{
    __shared__ float s_swT[NMEL*17];   // transposed [m][p]
    __shared__ float s_sb[17];
    for (int i = threadIdx.x; i < 17*NMEL; i += 256) {
        int p = i / NMEL, m = i % NMEL;
        s_swT[m*17 + p] = sw[i];
    }
    if (threadIdx.x < 17) s_sb[threadIdx.x] = sb[threadIdx.x];
    __syncthreads();

    const int lane = threadIdx.x & 31;
    const int gi   = lane >> 3;        // row group within warp (0..3)
    const int li   = lane & 7;         // lane within group
    const int warp = (blockIdx.x * blockDim.x + threadIdx.x) >> 5;   // 0..2047
    const int r    = warp*4 + gi;      // 0..8191
    const float alpha = *alpha_p;
    const float gf    = *gf_p;

    const ulonglong2* X2 = reinterpret_cast<const ulonglong2*>(x);
    const ulonglong2* W2 = reinterpret_cast<const ulonglong2*>(xw);

    u64 acc2[33];
    #pragma unroll
    for (int p = 0; p < 33; ++p) acc2[p] = 0ull;

    // k-slice: float4 indices k4 = li + 8*j, j = 0..15
    for (int j = 0; j < 16; ++j) {
        int k4 = li + 8*j;
        ulonglong2 xv = X2[(size_t)r*128 + k4];
        #pragma unroll
        for (int p = 0; p < 33; ++p) {
            ulonglong2 wv = W2[(size_t)p*128 + k4];
            acc2[p] = fma2(xv.x, wv.x, acc2[p]);
            acc2[p] = fma2(xv.y, wv.y, acc2[p]);
        }
    }

    float acc[33];
    #pragma unroll
    for (int p = 0; p < 33; ++p) {
        float lo, hi; unpack2(acc2[p], lo, hi);
        float v = lo + hi;
        v += __shfl_xor_sync(0xffffffffu, v, 4);
        v += __shfl_xor_sync(0xffffffffu, v, 2);
        v += __shfl_xor_sync(0xffffffffu, v, 1);
        acc[p] = v;                     // full row sum in all 8 lanes of group
    }

    // snr projection: lane li computes p in {li, li+8, li+16} when p <= 16
    float s[3];
    int   pl[3] = {li, li+8, li+16};
    #pragma unroll
    for (int q = 0; q < 3; ++q) s[q] = (pl[q] <= 16) ? s_sb[pl[q]] : 0.f;
    const float* sr = snr + (size_t)r*NMEL;
    #pragma unroll
    for (int m = 0; m < NMEL; ++m) {
        float sv = sr[m];
        #pragma unroll
        for (int q = 0; q < 3; ++q)
            if (pl[q] <= 16) s[q] = fmaf(sv, s_swT[m*17 + pl[q]], s[q]);
    }

    float* row = g_row + (size_t)r*ROWW;
    #pragma unroll
    for (int q = 0; q < 5; ++q) {
        int p = li + 8*q;
        if (p > 32) break;
        if (p == 0) {
            row[0] = acc[0] + s[0];
        } else if (p <= 16) {
            float sig = 1.f / (1.f + __expf(-s[q]));
            float fac = 1.f - alpha + alpha * (gf + (1.f - gf) * sig);
            row[p+3] = acc[p] * fac;        // row[4 + (p-1)]
        } else {
            row[p+3] = acc[p];              // row[20 + (p-17)]
        }
    }
}

// ---------------- pass 1: chunk-local scan (states only) ----------------
__global__ __launch_bounds__(256) void k_scanA(
    const float* __restrict__ x,   const float* __restrict__ Alog,
    const float* __restrict__ dtw, const float* __restrict__ dtb)
{
    __shared__ float s_row[TCH*ROWW];   // 5 KB
    const int bid = blockIdx.x;         // 0..511
    const int b  = bid >> 6;
    const int c  = (bid >> 1) & (NCH-1);
    const int dh = bid & 1;
    const int d  = dh*256 + threadIdx.x;

    size_t rbase = (size_t)b*LDIM + (size_t)c*TCH;
    {
        const float4* g4 = reinterpret_cast<const float4*>(g_row + rbase*ROWW);
        float4* s4p = reinterpret_cast<float4*>(s_row);
        for (int i = threadIdx.x; i < TCH*ROWW/4; i += 256) s4p[i] = g4[i];
    }
    __syncthreads();

    float A2[NST]; float a1;
    bool trick = load_A2(Alog, d, A2, a1);
    const float wd = dtw[d], bd = dtb[d];

    const float* xrow = x + rbase*DDIM + d;
    float cum = 0.f;
    u64 h2[8];
    #pragma unroll
    for (int k = 0; k < 8; ++k) h2[k] = 0ull;

    if (trick) {
        #pragma unroll 2
        for (int t = 0; t < TCH; ++t) {
            const float* srow = s_row + t*ROWW;
            float dts = srow[0];
            float del = softplusf(fmaf(dts, wd, bd));
            cum += del;
            float dx = del * xrow[(size_t)t*DDIM];
            u64 dx2 = pack2(dx, dx);
            u64 pw[8]; build_pw(fex2(a1*del), pw);

            ulonglong2 Bq0 = *reinterpret_cast<const ulonglong2*>(srow+4);
            ulonglong2 Bq1 = *reinterpret_cast<const ulonglong2*>(srow+8);
            ulonglong2 Bq2 = *reinterpret_cast<const ulonglong2*>(srow+12);
            ulonglong2 Bq3 = *reinterpret_cast<const ulonglong2*>(srow+16);
            u64 B2[8] = {Bq0.x, Bq0.y, Bq1.x, Bq1.y, Bq2.x, Bq2.y, Bq3.x, Bq3.y};
            #pragma unroll
            for (int k = 0; k < 8; ++k)
                h2[k] = fma2(pw[k], h2[k], mul2(dx2, B2[k]));
        }
    } else {
        float h[NST];
        #pragma unroll
        for (int n = 0; n < NST; ++n) h[n] = 0.f;
        for (int t = 0; t < TCH; ++t) {
            const float* srow = s_row + t*ROWW;
            float del = softplusf(fmaf(srow[0], wd, bd));
            cum += del;
            float dx = del * xrow[(size_t)t*DDIM];
            #pragma unroll
            for (int n = 0; n < NST; ++n)
                h[n] = fmaf(fex2(A2[n]*del), h[n], dx * srow[4+n]);
        }
        #pragma unroll
        for (int k = 0; k < 8; ++k) h2[k] = pack2(h[2*k], h[2*k+1]);
    }

    size_t hb = ((size_t)(b*NCH + c)*NST)*DDIM + d;
    #pragma unroll
    for (int k = 0; k < 8; ++k) {
        float lo, hi; unpack2(h2[k], lo, hi);
        g_hend[hb + (size_t)(2*k)*DDIM]   = lo;
        g_hend[hb + (size_t)(2*k+1)*DDIM] = hi;
    }
    g_cend[((size_t)b*NCH + c)*DDIM + d] = cum;
}

// ---------------- pass 2: cross-chunk combine, one thread per (b,d,n) ----------------
__global__ __launch_bounds__(256) void k_comb(const float* __restrict__ Alog)
{
    int tid = blockIdx.x * blockDim.x + threadIdx.x;   // 0..65535
    int d = tid & (DDIM-1);
    int n = (tid >> 9) & (NST-1);
    int b = tid >> 13;

    const float LOG2E = 1.4426950408889634f;
    float a = -__expf(Alog[d*NST + n]) * LOG2E;

    float h = 0.f;
    for (int c = 0; c < NCH; ++c) {
        size_t hb = ((size_t)(b*NCH + c)*NST + n)*DDIM + d;
        g_hin[hb] = h;
        float ce = g_cend[((size_t)b*NCH + c)*DDIM + d];
        h = fmaf(fex2(a * ce), h, g_hend[hb]);
    }
}

// ---------------- pass 3: full scan with true incoming state ----------------
__global__ __launch_bounds__(256) void k_scanB(
    const float* __restrict__ x,   const float* __restrict__ Alog,
    const float* __restrict__ dtw, const float* __restrict__ dtb,
    const float* __restrict__ Dprm, float* __restrict__ out)
{
    __shared__ float s_row[TCH*ROWW];
    const int bid = blockIdx.x;
    const int b  = bid >> 6;
    const int c  = (bid >> 1) & (NCH-1);
    const int dh = bid & 1;
    const int d  = dh*256 + threadIdx.x;

    size_t rbase = (size_t)b*LDIM + (size_t)c*TCH;
    {
        const float4* g4 = reinterpret_cast<const float4*>(g_row + rbase*ROWW);
        float4* s4p = reinterpret_cast<float4*>(s_row);
        for (int i = threadIdx.x; i < TCH*ROWW/4; i += 256) s4p[i] = g4[i];
    }
    __syncthreads();

    float A2[NST]; float a1;
    bool trick = load_A2(Alog, d, A2, a1);
    const float wd = dtw[d], bd = dtb[d], Dp = Dprm[d];

    u64 h2[8];
    size_t hb = ((size_t)(b*NCH + c)*NST)*DDIM + d;
    #pragma unroll
    for (int k = 0; k < 8; ++k)
        h2[k] = pack2(g_hin[hb + (size_t)(2*k)*DDIM],
                      g_hin[hb + (size_t)(2*k+1)*DDIM]);

    const float* xrow = x   + rbase*DDIM + d;
    float*       orow = out + rbase*DDIM + d;

    if (trick) {
        #pragma unroll 2
        for (int t = 0; t < TCH; ++t) {
            const float* srow = s_row + t*ROWW;
            float dts = srow[0];
            float del = softplusf(fmaf(dts, wd, bd));
            float xv  = xrow[(size_t)t*DDIM];
            float dx  = del * xv;
            u64 dx2 = pack2(dx, dx);
            u64 pw[8]; build_pw(fex2(a1*del), pw);

            ulonglong2 Bq0 = *reinterpret_cast<const ulonglong2*>(srow+4);
            ulonglong2 Bq1 = *reinterpret_cast<const ulonglong2*>(srow+8);
            ulonglong2 Bq2 = *reinterpret_cast<const ulonglong2*>(srow+12);
            ulonglong2 Bq3 = *reinterpret_cast<const ulonglong2*>(srow+16);
            ulonglong2 Cq0 = *reinterpret_cast<const ulonglong2*>(srow+20);
            ulonglong2 Cq1 = *reinterpret_cast<const ulonglong2*>(srow+24);
            ulonglong2 Cq2 = *reinterpret_cast<const ulonglong2*>(srow+28);
            ulonglong2 Cq3 = *reinterpret_cast<const ulonglong2*>(srow+32);
            u64 B2[8] = {Bq0.x, Bq0.y, Bq1.x, Bq1.y, Bq2.x, Bq2.y, Bq3.x, Bq3.y};
            u64 C2[8] = {Cq0.x, Cq0.y, Cq1.x, Cq1.y, Cq2.x, Cq2.y, Cq3.x, Cq3.y};

            u64 y2 = pack2(Dp * xv, 0.f);
            #pragma unroll
            for (int k = 0; k < 8; ++k) {
                h2[k] = fma2(pw[k], h2[k], mul2(dx2, B2[k]));
                y2    = fma2(h2[k], C2[k], y2);
            }
            float ylo, yhi; unpack2(y2, ylo, yhi);
            orow[(size_t)t*DDIM] = ylo + yhi;
        }
    } else {
        float h[NST];
        #pragma unroll
        for (int k = 0; k < 8; ++k) unpack2(h2[k], h[2*k], h[2*k+1]);
        for (int t = 0; t < TCH; ++t) {
            const float* srow = s_row + t*ROWW;
            float del = softplusf(fmaf(srow[0], wd, bd));
            float xv  = xrow[(size_t)t*DDIM];
            float dx  = del * xv;
            float y   = Dp * xv;
            #pragma unroll
            for (int n = 0; n < NST; ++n) {
                h[n] = fmaf(fex2(A2[n]*del), h[n], dx * srow[4+n]);
                y    = fmaf(h[n], srow[20+n], y);
            }
            orow[(size_t)t*DDIM] = y;
        }
    }
}

extern "C" void kernel_launch(void* const* d_in, const int* in_sizes, int n_in,
                              void* d_out, int out_size)
{
    const float* x    = (const float*)d_in[0];
    const float* snr  = (const float*)d_in[1];
    const float* xw   = (const float*)d_in[2];
    const float* sw   = (const float*)d_in[3];
    const float* sb   = (const float*)d_in[4];
    const float* dtw  = (const float*)d_in[5];
    const float* dtb  = (const float*)d_in[6];
    const float* Alog = (const float*)d_in[7];
    const float* Dp   = (const float*)d_in[8];
    const float* al   = (const float*)d_in[9];
    const float* gf   = (const float*)d_in[10];
    float* out = (float*)d_out;

    k_row  <<<256, 256>>>(x, snr, xw, sw, sb, al, gf);
    k_scanA<<<512, 256>>>(x, Alog, dtw, dtb);
    k_comb <<<256, 256>>>(Alog);
    k_scanB<<<512, 256>>>(x, Alog, dtw, dtb, Dp, out);
}

// round 6
// speedup vs baseline: 2.6308x; 1.0546x over previous
#include <cuda_runtime.h>
#include <math.h>

#define BDIM 8
#define LDIM 1024
#define DDIM 512
#define NST  16
#define NMEL 40
#define NCH  64
#define TCH  (LDIM/NCH)   // 16
#define ROWW 40           // [0]=dtsum, [4..19]=B_eff, [20..35]=C

typedef unsigned long long u64;

// Scratch (device globals; allocations are forbidden)
__device__ float g_row [BDIM*LDIM*ROWW];            // 1.31 MB
__device__ float g_hend[BDIM*NCH*NST*DDIM];         // 16 MB
__device__ float g_hin [BDIM*NCH*NST*DDIM];         // 16 MB
__device__ float g_cend[BDIM*NCH*DDIM];             // 1 MB

__device__ __forceinline__ float fex2(float x){
    float r; asm("ex2.approx.f32 %0,%1;" : "=f"(r) : "f"(x)); return r;
}
__device__ __forceinline__ float softplusf(float z){
    return (z > 15.f) ? z : __logf(1.f + __expf(z));
}
__device__ __forceinline__ u64 pack2(float lo, float hi){
    u64 r; asm("mov.b64 %0,{%1,%2};" : "=l"(r) : "f"(lo), "f"(hi)); return r;
}
__device__ __forceinline__ void unpack2(u64 v, float &lo, float &hi){
    asm("mov.b64 {%0,%1},%2;" : "=f"(lo), "=f"(hi) : "l"(v));
}
__device__ __forceinline__ u64 fma2(u64 a, u64 b, u64 c){
    u64 d; asm("fma.rn.f32x2 %0,%1,%2,%3;" : "=l"(d) : "l"(a), "l"(b), "l"(c)); return d;
}
__device__ __forceinline__ u64 mul2(u64 a, u64 b){
    u64 d; asm("mul.rn.f32x2 %0,%1,%2;" : "=l"(d) : "l"(a), "l"(b)); return d;
}

__device__ __forceinline__ bool load_A2(const float* __restrict__ Alog, int d,
                                        float (&A2)[NST], float &a1)
{
    const float LOG2E = 1.4426950408889634f;
    #pragma unroll
    for (int n = 0; n < NST; ++n)
        A2[n] = -__expf(Alog[d*NST + n]) * LOG2E;
    a1 = A2[0];
    bool ok = true;
    #pragma unroll
    for (int n = 0; n < NST; ++n) {
        float e = a1 * (float)(n+1);
        ok = ok && (fabsf(A2[n] - e) <= 1e-5f*fabsf(e) + 1e-7f);
    }
    return __all_sync(0xffffffffu, ok);
}

// Build pw[k] = (p^(2k+1), p^(2k+2)) with two depth-4 chains.
__device__ __forceinline__ void build_pw(float p, u64 (&pw)[8])
{
    float p2s = p * p;
    pw[0] = pack2(p, p2s);
    u64 s2 = pack2(p2s, p2s);
    u64 s4 = mul2(s2, s2);
    pw[1] = mul2(pw[0], s2);
    pw[2] = mul2(pw[0], s4);
    pw[3] = mul2(pw[1], s4);
    pw[4] = mul2(pw[2], s4);
    pw[5] = mul2(pw[3], s4);
    pw[6] = mul2(pw[4], s4);
    pw[7] = mul2(pw[5], s4);
}

// ---------------- pass 0: per-(b,l) projections ----------------
// W staged in dynamic smem (67.6 KB); 8 lanes per row, 4 rows per warp.
#define SMEM_KROW_FLOATS (33*512 + NMEL*17 + 32)
__global__ __launch_bounds__(256) void k_row(
    const float* __restrict__ x,  const float* __restrict__ snr,
    const float* __restrict__ xw, const float* __restrict__ sw,
    const float* __restrict__ sb, const float* __restrict__ alpha_p,
    const float* __restrict__ gf_p)
{
    extern __shared__ float smem[];
    float* s_w   = smem;                    // [33][512]
    float* s_swT = smem + 33*512;           // [NMEL][17]
    float* s_sb  = s_swT + NMEL*17;         // [17]

    {   // stage W coalesced as float4
        const float4* w4 = reinterpret_cast<const float4*>(xw);
        float4* s4 = reinterpret_cast<float4*>(s_w);
        for (int i = threadIdx.x; i < 33*128; i += 256) s4[i] = w4[i];
    }
    for (int i = threadIdx.x; i < 17*NMEL; i += 256) {
        int p = i / NMEL, m = i % NMEL;
        s_swT[m*17 + p] = sw[i];
    }
    if (threadIdx.x < 17) s_sb[threadIdx.x] = sb[threadIdx.x];
    __syncthreads();

    const int lane = threadIdx.x & 31;
    const int gi   = lane >> 3;        // row group within warp (0..3)
    const int li   = lane & 7;         // lane within group
    const int warp = (blockIdx.x * blockDim.x + threadIdx.x) >> 5;   // 0..2047
    const int r    = warp*4 + gi;      // 0..8191
    const float alpha = *alpha_p;
    const float gf    = *gf_p;

    const ulonglong2* X2 = reinterpret_cast<const ulonglong2*>(x);

    u64 acc2[33];
    #pragma unroll
    for (int p = 0; p < 33; ++p) acc2[p] = 0ull;

    for (int j = 0; j < 16; ++j) {
        int k4 = li + 8*j;
        ulonglong2 xv = X2[(size_t)r*128 + k4];
        #pragma unroll
        for (int p = 0; p < 33; ++p) {
            ulonglong2 wv = *reinterpret_cast<const ulonglong2*>(s_w + p*512 + k4*4);
            acc2[p] = fma2(xv.x, wv.x, acc2[p]);
            acc2[p] = fma2(xv.y, wv.y, acc2[p]);
        }
    }

    float acc[33];
    #pragma unroll
    for (int p = 0; p < 33; ++p) {
        float lo, hi; unpack2(acc2[p], lo, hi);
        float v = lo + hi;
        v += __shfl_xor_sync(0xffffffffu, v, 4);
        v += __shfl_xor_sync(0xffffffffu, v, 2);
        v += __shfl_xor_sync(0xffffffffu, v, 1);
        acc[p] = v;
    }

    float s[3];
    int   pl[3] = {li, li+8, li+16};
    #pragma unroll
    for (int q = 0; q < 3; ++q) s[q] = (pl[q] <= 16) ? s_sb[pl[q]] : 0.f;
    const float* sr = snr + (size_t)r*NMEL;
    #pragma unroll
    for (int m = 0; m < NMEL; ++m) {
        float sv = sr[m];
        #pragma unroll
        for (int q = 0; q < 3; ++q)
            if (pl[q] <= 16) s[q] = fmaf(sv, s_swT[m*17 + pl[q]], s[q]);
    }

    float* row = g_row + (size_t)r*ROWW;
    #pragma unroll
    for (int q = 0; q < 5; ++q) {
        int p = li + 8*q;
        if (p > 32) break;
        if (p == 0) {
            row[0] = acc[0] + s[0];
        } else if (p <= 16) {
            float sig = 1.f / (1.f + __expf(-s[q]));
            float fac = 1.f - alpha + alpha * (gf + (1.f - gf) * sig);
            row[p+3] = acc[p] * fac;
        } else {
            row[p+3] = acc[p];
        }
    }
}

// ---------------- pass 1: chunk-local scan (states only) ----------------
__global__ __launch_bounds__(256) void k_scanA(
    const float* __restrict__ x,   const float* __restrict__ Alog,
    const float* __restrict__ dtw, const float* __restrict__ dtb)
{
    __shared__ float s_row[TCH*ROWW];   // 2.5 KB
    const int bid = blockIdx.x;         // 0..1023
    const int b  = bid >> 7;
    const int c  = (bid >> 1) & (NCH-1);
    const int dh = bid & 1;
    const int d  = dh*256 + threadIdx.x;

    size_t rbase = (size_t)b*LDIM + (size_t)c*TCH;
    {
        const float4* g4 = reinterpret_cast<const float4*>(g_row + rbase*ROWW);
        float4* s4p = reinterpret_cast<float4*>(s_row);
        for (int i = threadIdx.x; i < TCH*ROWW/4; i += 256) s4p[i] = g4[i];
    }
    __syncthreads();

    float A2[NST]; float a1;
    bool trick = load_A2(Alog, d, A2, a1);
    const float wd = dtw[d], bd = dtb[d];

    const float* xrow = x + rbase*DDIM + d;
    float cum = 0.f;
    u64 h2[8];
    #pragma unroll
    for (int k = 0; k < 8; ++k) h2[k] = 0ull;

    if (trick) {
        #pragma unroll 2
        for (int t = 0; t < TCH; ++t) {
            const float* srow = s_row + t*ROWW;
            float del = softplusf(fmaf(srow[0], wd, bd));
            cum += del;
            float dx = del * xrow[(size_t)t*DDIM];
            u64 dx2 = pack2(dx, dx);
            u64 pw[8]; build_pw(fex2(a1*del), pw);

            ulonglong2 Bq0 = *reinterpret_cast<const ulonglong2*>(srow+4);
            ulonglong2 Bq1 = *reinterpret_cast<const ulonglong2*>(srow+8);
            ulonglong2 Bq2 = *reinterpret_cast<const ulonglong2*>(srow+12);
            ulonglong2 Bq3 = *reinterpret_cast<const ulonglong2*>(srow+16);
            u64 B2[8] = {Bq0.x, Bq0.y, Bq1.x, Bq1.y, Bq2.x, Bq2.y, Bq3.x, Bq3.y};
            #pragma unroll
            for (int k = 0; k < 8; ++k)
                h2[k] = fma2(pw[k], h2[k], mul2(dx2, B2[k]));
        }
    } else {
        float h[NST];
        #pragma unroll
        for (int n = 0; n < NST; ++n) h[n] = 0.f;
        for (int t = 0; t < TCH; ++t) {
            const float* srow = s_row + t*ROWW;
            float del = softplusf(fmaf(srow[0], wd, bd));
            cum += del;
            float dx = del * xrow[(size_t)t*DDIM];
            #pragma unroll
            for (int n = 0; n < NST; ++n)
                h[n] = fmaf(fex2(A2[n]*del), h[n], dx * srow[4+n]);
        }
        #pragma unroll
        for (int k = 0; k < 8; ++k) h2[k] = pack2(h[2*k], h[2*k+1]);
    }

    size_t hb = ((size_t)(b*NCH + c)*NST)*DDIM + d;
    #pragma unroll
    for (int k = 0; k < 8; ++k) {
        float lo, hi; unpack2(h2[k], lo, hi);
        g_hend[hb + (size_t)(2*k)*DDIM]   = lo;
        g_hend[hb + (size_t)(2*k+1)*DDIM] = hi;
    }
    g_cend[((size_t)b*NCH + c)*DDIM + d] = cum;
}

// ---------------- pass 2: cross-chunk combine, one thread per (b,d,n) ----------------
__global__ __launch_bounds__(256) void k_comb(const float* __restrict__ Alog)
{
    int tid = blockIdx.x * blockDim.x + threadIdx.x;   // 0..65535
    int d = tid & (DDIM-1);
    int n = (tid >> 9) & (NST-1);
    int b = tid >> 13;

    const float LOG2E = 1.4426950408889634f;
    float a = -__expf(Alog[d*NST + n]) * LOG2E;

    float h = 0.f;
    for (int c = 0; c < NCH; ++c) {
        size_t hb = ((size_t)(b*NCH + c)*NST + n)*DDIM + d;
        g_hin[hb] = h;
        float ce = g_cend[((size_t)b*NCH + c)*DDIM + d];
        h = fmaf(fex2(a * ce), h, g_hend[hb]);
    }
}

// ---------------- pass 3: full scan with true incoming state ----------------
__global__ __launch_bounds__(256) void k_scanB(
    const float* __restrict__ x,   const float* __restrict__ Alog,
    const float* __restrict__ dtw, const float* __restrict__ dtb,
    const float* __restrict__ Dprm, float* __restrict__ out)
{
    __shared__ float s_row[TCH*ROWW];
    const int bid = blockIdx.x;
    const int b  = bid >> 7;
    const int c  = (bid >> 1) & (NCH-1);
    const int dh = bid & 1;
    const int d  = dh*256 + threadIdx.x;

    size_t rbase = (size_t)b*LDIM + (size_t)c*TCH;
    {
        const float4* g4 = reinterpret_cast<const float4*>(g_row + rbase*ROWW);
        float4* s4p = reinterpret_cast<float4*>(s_row);
        for (int i = threadIdx.x; i < TCH*ROWW/4; i += 256) s4p[i] = g4[i];
    }
    __syncthreads();

    float A2[NST]; float a1;
    bool trick = load_A2(Alog, d, A2, a1);
    const float wd = dtw[d], bd = dtb[d], Dp = Dprm[d];

    u64 h2[8];
    size_t hb = ((size_t)(b*NCH + c)*NST)*DDIM + d;
    #pragma unroll
    for (int k = 0; k < 8; ++k)
        h2[k] = pack2(g_hin[hb + (size_t)(2*k)*DDIM],
                      g_hin[hb + (size_t)(2*k+1)*DDIM]);

    const float* xrow = x   + rbase*DDIM + d;
    float*       orow = out + rbase*DDIM + d;

    if (trick) {
        #pragma unroll 2
        for (int t = 0; t < TCH; ++t) {
            const float* srow = s_row + t*ROWW;
            float del = softplusf(fmaf(srow[0], wd, bd));
            float xv  = xrow[(size_t)t*DDIM];
            float dx  = del * xv;
            u64 dx2 = pack2(dx, dx);
            u64 pw[8]; build_pw(fex2(a1*del), pw);

            ulonglong2 Bq0 = *reinterpret_cast<const ulonglong2*>(srow+4);
            ulonglong2 Bq1 = *reinterpret_cast<const ulonglong2*>(srow+8);
            ulonglong2 Bq2 = *reinterpret_cast<const ulonglong2*>(srow+12);
            ulonglong2 Bq3 = *reinterpret_cast<const ulonglong2*>(srow+16);
            ulonglong2 Cq0 = *reinterpret_cast<const ulonglong2*>(srow+20);
            ulonglong2 Cq1 = *reinterpret_cast<const ulonglong2*>(srow+24);
            ulonglong2 Cq2 = *reinterpret_cast<const ulonglong2*>(srow+28);
            ulonglong2 Cq3 = *reinterpret_cast<const ulonglong2*>(srow+32);
            u64 B2[8] = {Bq0.x, Bq0.y, Bq1.x, Bq1.y, Bq2.x, Bq2.y, Bq3.x, Bq3.y};
            u64 C2[8] = {Cq0.x, Cq0.y, Cq1.x, Cq1.y, Cq2.x, Cq2.y, Cq3.x, Cq3.y};

            u64 y2 = pack2(Dp * xv, 0.f);
            #pragma unroll
            for (int k = 0; k < 8; ++k) {
                h2[k] = fma2(pw[k], h2[k], mul2(dx2, B2[k]));
                y2    = fma2(h2[k], C2[k], y2);
            }
            float ylo, yhi; unpack2(y2, ylo, yhi);
            orow[(size_t)t*DDIM] = ylo + yhi;
        }
    } else {
        float h[NST];
        #pragma unroll
        for (int k = 0; k < 8; ++k) unpack2(h2[k], h[2*k], h[2*k+1]);
        for (int t = 0; t < TCH; ++t) {
            const float* srow = s_row + t*ROWW;
            float del = softplusf(fmaf(srow[0], wd, bd));
            float xv  = xrow[(size_t)t*DDIM];
            float dx  = del * xv;
            float y   = Dp * xv;
            #pragma unroll
            for (int n = 0; n < NST; ++n) {
                h[n] = fmaf(fex2(A2[n]*del), h[n], dx * srow[4+n]);
                y    = fmaf(h[n], srow[20+n], y);
            }
            orow[(size_t)t*DDIM] = y;
        }
    }
}

extern "C" void kernel_launch(void* const* d_in, const int* in_sizes, int n_in,
                              void* d_out, int out_size)
{
    const float* x    = (const float*)d_in[0];
    const float* snr  = (const float*)d_in[1];
    const float* xw   = (const float*)d_in[2];
    const float* sw   = (const float*)d_in[3];
    const float* sb   = (const float*)d_in[4];
    const float* dtw  = (const float*)d_in[5];
    const float* dtb  = (const float*)d_in[6];
    const float* Alog = (const float*)d_in[7];
    const float* Dp   = (const float*)d_in[8];
    const float* al   = (const float*)d_in[9];
    const float* gf   = (const float*)d_in[10];
    float* out = (float*)d_out;

    static bool attr_set = false;
    if (!attr_set) {
        cudaFuncSetAttribute(k_row, cudaFuncAttributeMaxDynamicSharedMemorySize,
                             SMEM_KROW_FLOATS * (int)sizeof(float));
        attr_set = true;
    }

    k_row  <<<256, 256, SMEM_KROW_FLOATS*sizeof(float)>>>(x, snr, xw, sw, sb, al, gf);
    k_scanA<<<1024, 256>>>(x, Alog, dtw, dtb);
    k_comb <<<256, 256>>>(Alog);
    k_scanB<<<1024, 256>>>(x, Alog, dtw, dtb, Dp, out);
}